// round 17
// baseline (speedup 1.0000x reference)
#include <cuda_runtime.h>
#include <cstdint>

#define BSZ    64
#define BEAM   8
#define VOCAB  50257
#define KTOP   16
#define ROWS   (BSZ * BEAM)
#define NSPLIT 2
#define HHALF  ((VOCAB + NSPLIT - 1) / NSPLIT)   // 25129
#define THREADS 256
#define NWARP  (THREADS / 32)
#define CAP    2304               // fallback-lossless: 160 carry + 2048/iter + slack
#define FHI    160
#define NEG_INF __int_as_float(0xff800000)

typedef unsigned long long u64;

// Inter-CTA scratch (allocation-free)
__device__ float g_sv[ROWS][NSPLIT][KTOP];
__device__ int   g_si[ROWS][NSPLIT][KTOP];
__device__ int   g_arrive[BSZ];   // zero-init; finisher resets -> graph-replay safe

__device__ __forceinline__ unsigned ford(float f) {
    unsigned u = __float_as_uint(f);
    return u ^ ((unsigned)((int)u >> 31) | 0x80000000u);
}
__device__ __forceinline__ float funord(unsigned u) {
    return __uint_as_float((u & 0x80000000u) ? (u ^ 0x80000000u) : ~u);
}
__device__ __forceinline__ u64 umax64(u64 a, u64 b) { return a > b ? a : b; }
__device__ __forceinline__ float vloadf(const float* p) { return *(const volatile float*)p; }
__device__ __forceinline__ int   vloadi(const int*   p) { return *(const volatile int*)p; }

// Exact block top-16 of THREADS candidates (0 = empty, nonzero keys unique).
// Winners descending in win[0..15]. All threads must call.
__device__ __forceinline__ void block_topk16_1(u64 loc0, u64* win, u64* wtmp,
                                               int tid, int lane, int wid) {
    u64 loc = loc0;
    for (int r = 0; r < KTOP; ++r) {
        u64 lm = loc;
        u64 wm = lm;
#pragma unroll
        for (int off = 16; off; off >>= 1)
            wm = umax64(wm, __shfl_down_sync(0xffffffffu, wm, off));
        wm = __shfl_sync(0xffffffffu, wm, 0);
        if (lane == 0) wtmp[wid * KTOP + r] = wm;
        if (lm == wm && wm) loc = 0ull;
    }
    __syncthreads();
    if (wid == 0) {
        u64 m[4];                 // 8 warps * 16 = 128 keys, 4 per lane
#pragma unroll
        for (int s = 0; s < 4; ++s) m[s] = wtmp[lane + s * 32];
        for (int r = 0; r < KTOP; ++r) {
            u64 lm = umax64(umax64(m[0], m[1]), umax64(m[2], m[3]));
            u64 wm = lm;
#pragma unroll
            for (int off = 16; off; off >>= 1)
                wm = umax64(wm, __shfl_down_sync(0xffffffffu, wm, off));
            wm = __shfl_sync(0xffffffffu, wm, 0);
            if (lane == 0) win[r] = wm;
            if (lm == wm && wm) {
#pragma unroll
                for (int s = 0; s < 4; ++s) if (m[s] == wm) m[s] = 0ull;
            }
        }
    }
    __syncthreads();
}

// Rare big-buffer selection: smem-scan, low register footprint by design.
__device__ __noinline__ void topk16_scan(u64* buf, int C, u64* win, u64* wtmp,
                                         int tid, int lane, int wid) {
    for (int r = 0; r < KTOP; ++r) {
        u64 lm = 0ull;
        for (int e = tid; e < C; e += THREADS) lm = umax64(lm, buf[e]);
#pragma unroll
        for (int off = 16; off; off >>= 1)
            lm = umax64(lm, __shfl_down_sync(0xffffffffu, lm, off));
        if (lane == 0) wtmp[wid] = lm;
        __syncthreads();
        if (tid == 0) {
            u64 w = wtmp[0];
#pragma unroll
            for (int s = 1; s < NWARP; ++s) w = umax64(w, wtmp[s]);
            win[r] = w;
        }
        __syncthreads();
        u64 w = win[r];
        for (int e = tid; e < C; e += THREADS)
            if (buf[e] == w) buf[e] = 0ull;    // unique keys -> one owner
        __syncthreads();
    }
}

__global__ __launch_bounds__(THREADS, 5)
void dss_kernel(const float* __restrict__ lprobs,
                const float* __restrict__ scores,
                const int* __restrict__ stepp, int sdim,
                float* __restrict__ out) {
    __shared__ u64 buf[CAP];
    __shared__ u64 win[KTOP];
    __shared__ u64 wtmp[NWARP * KTOP];
    __shared__ int cnt;
    __shared__ int lastflag;

    const int bid  = blockIdx.x;
    const int r    = bid >> 1;        // (batch, beam) row
    const int h    = bid & 1;         // half index
    const int b    = r / BEAM;
    const int tid  = threadIdx.x;
    const int lane = tid & 31;
    const int wid  = tid >> 5;

    int step = *stepp;
    if (step < 0 || step > sdim) step = sdim;
    const float add = (step > 0) ? scores[r * sdim + (step - 1)] : 0.0f;

    if (tid == 0) cnt = 0;

    const float* rowbase = lprobs + (size_t)r * VOCAB;
    const int lo  = h * HHALF;
    const int len = (VOCAB - lo < HHALF) ? (VOCAB - lo) : HHALF;
    const float* basep = rowbase + lo;
    const uintptr_t addr = (uintptr_t)basep;
    const int pre  = (int)(((16u - (unsigned)(addr & 15u)) & 15u) >> 2);  // 0..3
    const int NV4  = (len - pre) >> 2;
    const int tail = len - pre - (NV4 << 2);
    const float4* b4 = (const float4*)(basep + pre);

    const int NITER = (NV4 + 2 * THREADS - 1) / (2 * THREADS);   // ~13
    const int NFULL = NV4 >> 9;                                  // ~12

    float T;
    float4 A0, A1, B0, B1;
    const float4 FILL = make_float4(NEG_INF, NEG_INF, NEG_INF, NEG_INF);

#define LD2(IT, R0, R1) do {                                   \
        int _i0 = (IT) * 2 * THREADS + tid;                    \
        int _i1 = _i0 + THREADS;                               \
        R0 = (_i0 < NV4) ? __ldcs(b4 + _i0) : FILL;            \
        R1 = (_i1 < NV4) ? __ldcs(b4 + _i1) : FILL;            \
    } while (0)

#define LD2U(IT, R0, R1) do {                                  \
        int _i0 = (IT) * 2 * THREADS + tid;                    \
        R0 = __ldcs(b4 + _i0);                                 \
        R1 = __ldcs(b4 + _i0 + THREADS);                       \
    } while (0)

#define LD2X(IT, R0, R1) do {                                  \
        if ((IT) < NFULL)       LD2U(IT, R0, R1);              \
        else if ((IT) < NITER)  LD2(IT, R0, R1);               \
    } while (0)

    // gate on raw max + single add (fp add monotone); slow path: per-element
    // predicated atomic append; bounds-checked ticket -> overflow triggers
    // the exact fallback pass (statistically never).
#define PROC(IT, R0, R1) do {                                                 \
        float m8 = fmaxf(fmaxf(fmaxf(R0.x, R0.y), fmaxf(R0.z, R0.w)),         \
                         fmaxf(fmaxf(R1.x, R1.y), fmaxf(R1.z, R1.w)));        \
        if (__any_sync(0xffffffffu, m8 + add >= T)) {                         \
            const int _i0 = (IT) * 2 * THREADS + tid;                         \
            float vv[8] = {R0.x + add, R0.y + add, R0.z + add, R0.w + add,    \
                           R1.x + add, R1.y + add, R1.z + add, R1.w + add};   \
            _Pragma("unroll")                                                 \
            for (int j = 0; j < 8; ++j) {                                     \
                if (vv[j] >= T) {                                             \
                    int p = atomicAdd(&cnt, 1);                               \
                    unsigned gidx = (unsigned)(lo + pre +                     \
                        (_i0 + (j >> 2) * THREADS) * 4 + (j & 3));            \
                    if (p < CAP)                                              \
                        buf[p] = ((u64)ford(vv[j]) << 32) | (unsigned)~gidx;  \
                }                                                             \
            }                                                                 \
        }                                                                     \
    } while (0)

#define PROLOGUE() do {                                                       \
        if (tid < pre) {                                                      \
            float v = basep[tid] + add;                                       \
            if (v >= T) {                                                     \
                int p = atomicAdd(&cnt, 1);                                   \
                if (p < CAP) buf[p] = ((u64)ford(v) << 32)                    \
                                      | (unsigned)~((unsigned)(lo + tid));    \
            }                                                                 \
        }                                                                     \
        int t2 = tid - 64;                                                    \
        if (t2 >= 0 && t2 < tail) {                                           \
            int gl = pre + (NV4 << 2) + t2;                                   \
            float v = basep[gl] + add;                                        \
            if (v >= T) {                                                     \
                int p = atomicAdd(&cnt, 1);                                   \
                if (p < CAP) buf[p] = ((u64)ford(v) << 32)                    \
                                      | (unsigned)~((unsigned)(lo + gl));     \
            }                                                                 \
        }                                                                     \
    } while (0)

    // ---------- PASS 0: fixed statistical threshold, ZERO barriers ----------
    LD2X(0, A0, A1);
    LD2X(1, B0, B1);
    T = add + 2.8f;          // P(N(0,1) >= 2.8) ~ 2.55e-3 -> ~64 survivors/half
    __syncthreads();         // cnt = 0 visible
    PROLOGUE();

    {
        int s = 0;
        for (; s + 1 < NITER; s += 2) {
            PROC(s, A0, A1);
            LD2X(s + 2, A0, A1);
            PROC(s + 1, B0, B1);
            LD2X(s + 3, B0, B1);
        }
        if (s < NITER) PROC(s, A0, A1);   // NITER odd -> even index -> A buffer
    }

    __syncthreads();
    int Cend = cnt;
    __syncthreads();

    // ------- FALLBACK (adversarial only): exact seed + compaction loop -------
    if (Cend < KTOP || Cend > CAP) {
        if (tid == 0) cnt = 0;
        LD2(0, A0, A1);
        {   // seed T = 16th of 256 per-thread maxima -> guarantees >=16 survivors
            float mx = fmaxf(fmaxf(fmaxf(A0.x, A0.y), fmaxf(A0.z, A0.w)),
                             fmaxf(fmaxf(A1.x, A1.y), fmaxf(A1.z, A1.w))) + add;
            block_topk16_1(((u64)ford(mx) << 32) | (unsigned)~((unsigned)tid),
                           win, wtmp, tid, lane, wid);   // also syncs cnt=0
            T = funord((unsigned)(win[KTOP - 1] >> 32));
        }
        PROLOGUE();
        for (int j2 = 0; j2 < NITER; ++j2) {
            LD2(j2, A0, A1);
            PROC(j2, A0, A1);
            __syncthreads();
            int Cg = cnt;
            __syncthreads();
            if (Cg > FHI) {                  // keeps cnt <= FHI + 2048 < CAP
                topk16_scan(buf, Cg, win, wtmp, tid, lane, wid);
                if (tid < KTOP) buf[tid] = win[tid];
                if (tid == 0) cnt = KTOP;
                T = funord((unsigned)(win[KTOP - 1] >> 32));
                __syncthreads();
            }
        }
        __syncthreads();
        Cend = cnt;
        __syncthreads();
    }

    // ---------- exact top-16 of this half ----------
    if (Cend <= THREADS) {
        block_topk16_1((tid < Cend) ? buf[tid] : 0ull, win, wtmp, tid, lane, wid);
    } else {
        topk16_scan(buf, Cend, win, wtmp, tid, lane, wid);
    }
    if (tid < KTOP) {
        u64 w = win[tid];
        g_sv[r][h][tid] = funord((unsigned)(w >> 32));
        g_si[r][h][tid] = (int)~((unsigned)w);
    }
    __threadfence();
    __syncthreads();

    // last of the batch's 16 CTAs merges and finishes
    if (tid == 0)
        lastflag = (atomicAdd(&g_arrive[b], 1) == NSPLIT * BEAM - 1) ? 1 : 0;
    __syncthreads();
    if (!lastflag) return;
    __threadfence();   // acquire: see all halves' writes

    // per-beam warp merge: 32 union keys -> ordered top-16 (== row top-16)
    {
        const int beam = wid;
        const int hh = lane >> 4, pos = lane & 15;
        const int rr = b * BEAM + beam;
        float v  = vloadf(&g_sv[rr][hh][pos]);
        int   ix = vloadi(&g_si[rr][hh][pos]);
        u64 k = ((u64)ford(v) << 32) | (unsigned)~((unsigned)ix);
        for (int r2 = 0; r2 < KTOP; ++r2) {
            u64 wm = k;
#pragma unroll
            for (int off = 16; off; off >>= 1)
                wm = umax64(wm, __shfl_down_sync(0xffffffffu, wm, off));
            wm = __shfl_sync(0xffffffffu, wm, 0);
            if (k == wm && k) k = 0ull;
            if (lane == 0) buf[beam * KTOP + r2] = wm;
        }
    }
    __syncthreads();

    float* out_scores = out;
    float* out_idx    = out + BSZ * KTOP;
    float* out_beam   = out + 2 * BSZ * KTOP;

    if (step == 0) {
        if (tid < KTOP) {
            u64 w = buf[tid];                 // beam 0 ordered row top-16
            out_scores[b * KTOP + tid] = funord((unsigned)(w >> 32));
            out_idx[b * KTOP + tid]    = (float)(int)~((unsigned)w);
            out_beam[b * KTOP + tid]   = 0.0f;
        }
        if (tid == 0) g_arrive[b] = 0;
        return;
    }

    {
        u64 k = 0ull;
        if (tid < BEAM * KTOP) {
            const int pos = tid & 15;
            const float v = funord((unsigned)(buf[tid] >> 32))
                            - (float)(pos + 1) * 0.5f;
            k = ((u64)ford(v) << 32) | (unsigned)~((unsigned)tid);
        }
        block_topk16_1(k, win, wtmp, tid, lane, wid);
    }
    if (tid < KTOP) {
        u64 w = win[tid];
        const int j = (int)~((unsigned)w);       // flat candidate == reference fi
        out_scores[b * KTOP + tid] = funord((unsigned)(w >> 32));
        out_idx[b * KTOP + tid]    = (float)(int)~((unsigned)buf[j]);
        out_beam[b * KTOP + tid]   = (float)(j >> 4);
    }
    if (tid == 0) g_arrive[b] = 0;
}

extern "C" void kernel_launch(void* const* d_in, const int* in_sizes, int n_in,
                              void* d_out, int out_size) {
    const float* lprobs = (const float*)d_in[0];
    const float* scores = (const float*)d_in[1];
    const int*   stepp  = (const int*)d_in[2];
    const int sdim = in_sizes[1] / ROWS;

    dss_kernel<<<ROWS * NSPLIT, THREADS>>>(lprobs, scores, stepp, sdim, (float*)d_out);
}